// round 1
// baseline (speedup 1.0000x reference)
#include <cuda_runtime.h>

#define BSZ   16
#define TSEQ  2048
#define NDIM  32
#define NH    4
#define HS    8

// Scratch (device globals — no allocation allowed)
__device__ float g_Q[BSZ*NH*TSEQ*HS];
__device__ float g_K[BSZ*NH*TSEQ*HS];
__device__ float g_V[BSZ*NH*TSEQ*HS];
__device__ float g_Z[BSZ*TSEQ*NDIM];

typedef unsigned long long u64;

__device__ __forceinline__ u64 f2_pack(float lo, float hi){
    u64 r; asm("mov.b64 %0,{%1,%2};":"=l"(r):"f"(lo),"f"(hi)); return r;
}
__device__ __forceinline__ void f2_unpack(u64 v, float& lo, float& hi){
    asm("mov.b64 {%0,%1},%2;":"=f"(lo),"=f"(hi):"l"(v));
}
__device__ __forceinline__ u64 f2_fma(u64 a, u64 b, u64 c){
    u64 d; asm("fma.rn.f32x2 %0,%1,%2,%3;":"=l"(d):"l"(a),"l"(b),"l"(c)); return d;
}
__device__ __forceinline__ u64 f2_mul(u64 a, u64 b){
    u64 d; asm("mul.rn.f32x2 %0,%1,%2;":"=l"(d):"l"(a),"l"(b)); return d;
}
__device__ __forceinline__ float fast_ex2(float x){
    float r; asm("ex2.approx.ftz.f32 %0,%1;":"=f"(r):"f"(x)); return r;
}

// ---------------------------------------------------------------------------
// Kernel 1: fused QKV projection.  One thread per token.
// y[d] = b[d] + sum_c x[c] * W[d][c]   (nn.Linear: x @ W^T + b)
// Output layout: [b][h][t][8]
// ---------------------------------------------------------------------------
__global__ __launch_bounds__(256) void qkv_kernel(
    const float* __restrict__ x,
    const float* __restrict__ Wq, const float* __restrict__ bq,
    const float* __restrict__ Wk, const float* __restrict__ bk,
    const float* __restrict__ Wv, const float* __restrict__ bv)
{
    __shared__ float4 sW[3*256];   // 3 matrices of 32x32 floats = 256 float4 each
    __shared__ float  sB[96];
    int tid = threadIdx.x;
    sW[tid]       = ((const float4*)Wq)[tid];
    sW[256+tid]   = ((const float4*)Wk)[tid];
    sW[512+tid]   = ((const float4*)Wv)[tid];
    if (tid < 96) sB[tid] = (tid < 32) ? bq[tid] : (tid < 64 ? bk[tid-32] : bv[tid-64]);
    __syncthreads();

    int tok = blockIdx.x * 256 + tid;          // 0 .. B*T-1
    int b = tok >> 11;
    int t = tok & (TSEQ - 1);

    float xv[32];
    const float4* xr = (const float4*)(x + (size_t)tok * NDIM);
#pragma unroll
    for (int i = 0; i < 8; i++) {
        float4 v = xr[i];
        xv[4*i] = v.x; xv[4*i+1] = v.y; xv[4*i+2] = v.z; xv[4*i+3] = v.w;
    }

#pragma unroll
    for (int m = 0; m < 3; m++) {
        float out[32];
#pragma unroll
        for (int d = 0; d < 32; d++) {
            float acc = sB[m*32 + d];
#pragma unroll
            for (int c = 0; c < 8; c++) {
                float4 w = sW[m*256 + d*8 + c];
                acc = fmaf(xv[4*c],   w.x,
                      fmaf(xv[4*c+1], w.y,
                      fmaf(xv[4*c+2], w.z,
                      fmaf(xv[4*c+3], w.w, acc))));
            }
            out[d] = acc;
        }
        float* dst = (m == 0) ? g_Q : (m == 1) ? g_K : g_V;
#pragma unroll
        for (int h = 0; h < NH; h++) {
            float4* p = (float4*)&dst[(((size_t)(b*NH + h)) * TSEQ + t) * HS];
            p[0] = make_float4(out[h*8+0], out[h*8+1], out[h*8+2], out[h*8+3]);
            p[1] = make_float4(out[h*8+4], out[h*8+5], out[h*8+6], out[h*8+7]);
        }
    }
}

// ---------------------------------------------------------------------------
// Kernel 2: causal flash attention (no online max; scores are small, exp2 safe).
// Block = (batch b, 64-query tile). Thread = (query_in_tile, head).
// K/V staged through smem tiles of 64 keys in layout [j][h][8].
// All math through packed f32x2 FMA (2 fp32 FMAs / instr).
// ---------------------------------------------------------------------------
__global__ __launch_bounds__(256) void attn_kernel()
{
    __shared__ float4 sK[64][NH][2];
    __shared__ float4 sV[64][NH][2];
    int tid = threadIdx.x;
    int b  = blockIdx.y;
    int qt = (int)gridDim.x - 1 - (int)blockIdx.x;  // heavy tiles first
    int ql = tid >> 2;
    int h  = tid & 3;
    int i  = qt * 64 + ql;

    // scale = 1/sqrt(head_size) * log2(e), folded into q so exp2(dot) == softmax weight
    const float SC = 0.35355339059327f * 1.44269504088896f;
    const float4* qp = (const float4*)&g_Q[(((size_t)(b*NH + h)) * TSEQ + i) * HS];
    float4 qa = qp[0], qb = qp[1];
    u64 q01 = f2_pack(qa.x*SC, qa.y*SC), q23 = f2_pack(qa.z*SC, qa.w*SC);
    u64 q45 = f2_pack(qb.x*SC, qb.y*SC), q67 = f2_pack(qb.z*SC, qb.w*SC);

    u64 a01 = 0ull, a23 = 0ull, a45 = 0ull, a67 = 0ull;  // bitwise (0.f,0.f)
    float l = 0.f;

    int nkt = qt + 1;
    for (int kt = 0; kt < nkt; kt++) {
        int j0 = kt * 64;
        __syncthreads();   // previous tile fully consumed
#pragma unroll
        for (int f = tid; f < 512; f += 256) {
            int d4 = f & 1, hh = (f >> 1) & 3, jl = f >> 3;
            size_t g = (((size_t)(b*NH + hh)) * TSEQ + (j0 + jl)) * 2 + d4;
            sK[jl][hh][d4] = ((const float4*)g_K)[g];
            sV[jl][hh][d4] = ((const float4*)g_V)[g];
        }
        __syncthreads();

        int jmax = (kt == nkt - 1) ? (ql + 1) : 64;   // causal mask only on diagonal tile
        for (int jl = 0; jl < jmax; jl++) {
            const ulonglong2* kp = (const ulonglong2*)&sK[jl][h][0];
            ulonglong2 k0 = kp[0], k1 = kp[1];
            u64 t0 = f2_mul(q01, k0.x);
            t0 = f2_fma(q23, k0.y, t0);
            u64 t1 = f2_mul(q45, k1.x);
            t1 = f2_fma(q67, k1.y, t1);
            float s0, s1, s2, s3;
            f2_unpack(t0, s0, s1);
            f2_unpack(t1, s2, s3);
            float p = fast_ex2((s0 + s1) + (s2 + s3));

            const ulonglong2* vp = (const ulonglong2*)&sV[jl][h][0];
            ulonglong2 v0 = vp[0], v1 = vp[1];
            u64 pp = f2_pack(p, p);
            a01 = f2_fma(pp, v0.x, a01);
            a23 = f2_fma(pp, v0.y, a23);
            a45 = f2_fma(pp, v1.x, a45);
            a67 = f2_fma(pp, v1.y, a67);
            l += p;
        }
    }

    float inv = __frcp_rn(l);   // l >= exp(s_ii) > 0 always
    float o0,o1,o2,o3,o4,o5,o6,o7;
    f2_unpack(a01, o0, o1); f2_unpack(a23, o2, o3);
    f2_unpack(a45, o4, o5); f2_unpack(a67, o6, o7);
    float4* zp = (float4*)&g_Z[((size_t)b * TSEQ + i) * NDIM + h * HS];
    zp[0] = make_float4(o0*inv, o1*inv, o2*inv, o3*inv);
    zp[1] = make_float4(o4*inv, o5*inv, o6*inv, o7*inv);
}

// ---------------------------------------------------------------------------
// Kernel 3: output projection. One thread per token.
// ---------------------------------------------------------------------------
__global__ __launch_bounds__(256) void proj_kernel(
    const float* __restrict__ Wp, const float* __restrict__ bp,
    float* __restrict__ out)
{
    __shared__ float4 sW[256];
    __shared__ float  sB[32];
    int tid = threadIdx.x;
    sW[tid] = ((const float4*)Wp)[tid];
    if (tid < 32) sB[tid] = bp[tid];
    __syncthreads();

    int tok = blockIdx.x * 256 + tid;
    float zv[32];
    const float4* zr = (const float4*)&g_Z[(size_t)tok * NDIM];
#pragma unroll
    for (int i = 0; i < 8; i++) {
        float4 v = zr[i];
        zv[4*i] = v.x; zv[4*i+1] = v.y; zv[4*i+2] = v.z; zv[4*i+3] = v.w;
    }
    float o[32];
#pragma unroll
    for (int d = 0; d < 32; d++) {
        float acc = sB[d];
#pragma unroll
        for (int c = 0; c < 8; c++) {
            float4 w = sW[d*8 + c];
            acc = fmaf(zv[4*c],   w.x,
                  fmaf(zv[4*c+1], w.y,
                  fmaf(zv[4*c+2], w.z,
                  fmaf(zv[4*c+3], w.w, acc))));
        }
        o[d] = acc;
    }
    float4* op = (float4*)&out[(size_t)tok * NDIM];
#pragma unroll
    for (int c = 0; c < 8; c++)
        op[c] = make_float4(o[4*c], o[4*c+1], o[4*c+2], o[4*c+3]);
}

// ---------------------------------------------------------------------------
extern "C" void kernel_launch(void* const* d_in, const int* in_sizes, int n_in,
                              void* d_out, int out_size)
{
    const float* x  = (const float*)d_in[0];
    const float* Wq = (const float*)d_in[1];
    const float* bq = (const float*)d_in[2];
    const float* Wk = (const float*)d_in[3];
    const float* bk = (const float*)d_in[4];
    const float* Wv = (const float*)d_in[5];
    const float* bv = (const float*)d_in[6];
    const float* Wp = (const float*)d_in[7];
    const float* bp = (const float*)d_in[8];
    float* out = (float*)d_out;

    qkv_kernel<<<(BSZ*TSEQ)/256, 256>>>(x, Wq, bq, Wk, bk, Wv, bv);
    attn_kernel<<<dim3(TSEQ/64, BSZ), 256>>>();
    proj_kernel<<<(BSZ*TSEQ)/256, 256>>>(Wp, bp, out);
}

// round 2
// speedup vs baseline: 2.1409x; 2.1409x over previous
#include <cuda_runtime.h>

#define BSZ   16
#define TSEQ  2048
#define NDIM  32
#define NH    4
#define HS    8
#define TQ    64          // queries per block (attn)
#define TK    64          // keys per smem tile
#define NPAIR (TK/2)      // 32 key-pairs per tile
#define RS    10          // smem row stride in u64 (80B: keeps 16B align per row)
#define HSZ   (NPAIR*RS + 2)   // u64 per head region (padded)

// Scratch (device globals — no allocation allowed)
__device__ float g_Q [BSZ*NH*TSEQ*HS];            // [b][h][t][d]
__device__ float g_K2[BSZ*NH*HS*TSEQ];            // [b][h][d][t]  (dim-major!)
__device__ float g_V2[BSZ*NH*HS*TSEQ];            // [b][h][d][t]
__device__ float g_Z [BSZ*TSEQ*NDIM];

typedef unsigned long long u64;

__device__ __forceinline__ u64 f2_pack(float lo, float hi){
    u64 r; asm("mov.b64 %0,{%1,%2};":"=l"(r):"f"(lo),"f"(hi)); return r;
}
__device__ __forceinline__ void f2_unpack(u64 v, float& lo, float& hi){
    asm("mov.b64 {%0,%1},%2;":"=f"(lo),"=f"(hi):"l"(v));
}
__device__ __forceinline__ u64 f2_fma(u64 a, u64 b, u64 c){
    u64 d; asm("fma.rn.f32x2 %0,%1,%2,%3;":"=l"(d):"l"(a),"l"(b),"l"(c)); return d;
}
__device__ __forceinline__ u64 f2_mul(u64 a, u64 b){
    u64 d; asm("mul.rn.f32x2 %0,%1,%2;":"=l"(d):"l"(a),"l"(b)); return d;
}
__device__ __forceinline__ u64 f2_add(u64 a, u64 b){
    u64 d; asm("add.rn.f32x2 %0,%1,%2;":"=l"(d):"l"(a),"l"(b)); return d;
}
__device__ __forceinline__ float fast_ex2(float x){
    float r; asm("ex2.approx.ftz.f32 %0,%1;":"=f"(r):"f"(x)); return r;
}

// ---------------------------------------------------------------------------
// Kernel 1: QKV projection. grid=(128,3): blockIdx.y selects matrix.
// Q stored token-major [b][h][t][8]; K,V stored dim-major [b][h][d][t]
// (coalesced 4B stores per (h,d); enables u64 key-pair loads in attn).
// ---------------------------------------------------------------------------
__global__ __launch_bounds__(256) void qkv_kernel(
    const float* __restrict__ x,
    const float* __restrict__ Wq, const float* __restrict__ bq,
    const float* __restrict__ Wk, const float* __restrict__ bk,
    const float* __restrict__ Wv, const float* __restrict__ bv)
{
    __shared__ float4 sW[256];
    __shared__ float  sB[32];
    int m   = blockIdx.y;
    int tid = threadIdx.x;
    const float* W  = (m == 0) ? Wq : (m == 1) ? Wk : Wv;
    const float* bb = (m == 0) ? bq : (m == 1) ? bk : bv;
    sW[tid] = ((const float4*)W)[tid];
    if (tid < 32) sB[tid] = bb[tid];
    __syncthreads();

    int tok = blockIdx.x * 256 + tid;
    int b = tok >> 11;
    int t = tok & (TSEQ - 1);

    float xv[32];
    const float4* xr = (const float4*)(x + (size_t)tok * NDIM);
#pragma unroll
    for (int i = 0; i < 8; i++) {
        float4 v = xr[i];
        xv[4*i] = v.x; xv[4*i+1] = v.y; xv[4*i+2] = v.z; xv[4*i+3] = v.w;
    }

    float out[32];
#pragma unroll
    for (int d = 0; d < 32; d++) {
        float acc = sB[d];
#pragma unroll
        for (int c = 0; c < 8; c++) {
            float4 w = sW[d*8 + c];
            acc = fmaf(xv[4*c],   w.x,
                  fmaf(xv[4*c+1], w.y,
                  fmaf(xv[4*c+2], w.z,
                  fmaf(xv[4*c+3], w.w, acc))));
        }
        out[d] = acc;
    }

    if (m == 0) {
#pragma unroll
        for (int h = 0; h < NH; h++) {
            float4* p = (float4*)&g_Q[(((size_t)(b*NH + h)) * TSEQ + t) * HS];
            p[0] = make_float4(out[h*8+0], out[h*8+1], out[h*8+2], out[h*8+3]);
            p[1] = make_float4(out[h*8+4], out[h*8+5], out[h*8+6], out[h*8+7]);
        }
    } else {
        float* dst = (m == 1) ? g_K2 : g_V2;
#pragma unroll
        for (int d = 0; d < 32; d++) {
            int h = d >> 3, dd = d & 7;
            dst[(((size_t)(b*NH + h)) * HS + dd) * TSEQ + t] = out[d];
        }
    }
}

// ---------------------------------------------------------------------------
// Kernel 2: causal attention, key-pair-packed f32x2 math.
// grid = (BSZ, TSEQ/TQ); block = 128 thr = 4 warps; warp = one head.
// Lane qg handles queries {2qg, 2qg+1}. Inner loop: one key-PAIR per step;
// packed dot gives both scores in one f32x2 chain; packed p drives PV.
// Smem rows are read warp-uniform -> pure broadcast, conflict-free.
// ---------------------------------------------------------------------------
__global__ __launch_bounds__(128) void attn_kernel()
{
    __shared__ u64 sm[2*NH*HSZ];     // K then V, per-head regions

    int tid = threadIdx.x;
    int h   = tid >> 5;              // warp id = head
    int qg  = tid & 31;              // lane = query group
    int b   = blockIdx.x;
    int qt  = (int)gridDim.y - 1 - (int)blockIdx.y;   // heavy tiles first
    int i0  = qt * TQ + 2*qg;

    const float SC = 0.35355339059327f * 1.44269504088896f; // 1/sqrt(8)*log2(e)

    // load 2 queries, pre-scaled, lane-duplicated
    const float4* qp = (const float4*)&g_Q[(((size_t)(b*NH + h)) * TSEQ + i0) * HS];
    float4 qA = qp[0], qB = qp[1], qC = qp[2], qD = qp[3];
    u64 q0[8], q1[8];
    q0[0]=f2_pack(qA.x*SC,qA.x*SC); q0[1]=f2_pack(qA.y*SC,qA.y*SC);
    q0[2]=f2_pack(qA.z*SC,qA.z*SC); q0[3]=f2_pack(qA.w*SC,qA.w*SC);
    q0[4]=f2_pack(qB.x*SC,qB.x*SC); q0[5]=f2_pack(qB.y*SC,qB.y*SC);
    q0[6]=f2_pack(qB.z*SC,qB.z*SC); q0[7]=f2_pack(qB.w*SC,qB.w*SC);
    q1[0]=f2_pack(qC.x*SC,qC.x*SC); q1[1]=f2_pack(qC.y*SC,qC.y*SC);
    q1[2]=f2_pack(qC.z*SC,qC.z*SC); q1[3]=f2_pack(qC.w*SC,qC.w*SC);
    q1[4]=f2_pack(qD.x*SC,qD.x*SC); q1[5]=f2_pack(qD.y*SC,qD.y*SC);
    q1[6]=f2_pack(qD.z*SC,qD.z*SC); q1[7]=f2_pack(qD.w*SC,qD.w*SC);

    u64 a0[8], a1[8];
#pragma unroll
    for (int d = 0; d < 8; d++) { a0[d] = 0ull; a1[d] = 0ull; }
    u64 l0 = 0ull, l1 = 0ull;

    const u64* kr = sm + h*HSZ;
    const u64* vr = sm + NH*HSZ + h*HSZ;

#define PAIR_BODY(JP, MASK0)                                               \
    {                                                                      \
        const ulonglong2* kp2 = (const ulonglong2*)(kr + (JP)*RS);         \
        ulonglong2 ka = kp2[0], kb = kp2[1], kc = kp2[2], kd = kp2[3];     \
        u64 t0 = f2_mul(q0[0], ka.x);                                      \
        t0 = f2_fma(q0[1], ka.y, t0);                                      \
        t0 = f2_fma(q0[2], kb.x, t0);                                      \
        t0 = f2_fma(q0[3], kb.y, t0);                                      \
        t0 = f2_fma(q0[4], kc.x, t0);                                      \
        t0 = f2_fma(q0[5], kc.y, t0);                                      \
        t0 = f2_fma(q0[6], kd.x, t0);                                      \
        t0 = f2_fma(q0[7], kd.y, t0);                                      \
        u64 t1 = f2_mul(q1[0], ka.x);                                      \
        t1 = f2_fma(q1[1], ka.y, t1);                                      \
        t1 = f2_fma(q1[2], kb.x, t1);                                      \
        t1 = f2_fma(q1[3], kb.y, t1);                                      \
        t1 = f2_fma(q1[4], kc.x, t1);                                      \
        t1 = f2_fma(q1[5], kc.y, t1);                                      \
        t1 = f2_fma(q1[6], kd.x, t1);                                      \
        t1 = f2_fma(q1[7], kd.y, t1);                                      \
        float s0e, s0o, s1e, s1o;                                          \
        f2_unpack(t0, s0e, s0o);                                           \
        f2_unpack(t1, s1e, s1o);                                           \
        float p0o = (MASK0) ? 0.0f : fast_ex2(s0o);                        \
        u64 pp0 = f2_pack(fast_ex2(s0e), p0o);                             \
        u64 pp1 = f2_pack(fast_ex2(s1e), fast_ex2(s1o));                   \
        l0 = f2_add(l0, pp0);                                              \
        l1 = f2_add(l1, pp1);                                              \
        const ulonglong2* vp2 = (const ulonglong2*)(vr + (JP)*RS);         \
        ulonglong2 va = vp2[0], vb = vp2[1], vc = vp2[2], vd = vp2[3];     \
        a0[0] = f2_fma(pp0, va.x, a0[0]);  a1[0] = f2_fma(pp1, va.x, a1[0]); \
        a0[1] = f2_fma(pp0, va.y, a0[1]);  a1[1] = f2_fma(pp1, va.y, a1[1]); \
        a0[2] = f2_fma(pp0, vb.x, a0[2]);  a1[2] = f2_fma(pp1, vb.x, a1[2]); \
        a0[3] = f2_fma(pp0, vb.y, a0[3]);  a1[3] = f2_fma(pp1, vb.y, a1[3]); \
        a0[4] = f2_fma(pp0, vc.x, a0[4]);  a1[4] = f2_fma(pp1, vc.x, a1[4]); \
        a0[5] = f2_fma(pp0, vc.y, a0[5]);  a1[5] = f2_fma(pp1, vc.y, a1[5]); \
        a0[6] = f2_fma(pp0, vd.x, a0[6]);  a1[6] = f2_fma(pp1, vd.x, a1[6]); \
        a0[7] = f2_fma(pp0, vd.y, a0[7]);  a1[7] = f2_fma(pp1, vd.y, a1[7]); \
    }

    int nkt = qt + 1;
    for (int kt = 0; kt < nkt; kt++) {
        int j0 = kt * TK;
        __syncthreads();
        // stage: each thread copies one K row and one V row (8 u64 each).
        {
            size_t src = ((size_t)(b*NH + h)) * HS * TSEQ + (j0 + 2*qg);
            u64* dK = sm + h*HSZ + qg*RS;
            u64* dV = sm + NH*HSZ + h*HSZ + qg*RS;
#pragma unroll
            for (int d = 0; d < 8; d++) {
                dK[d] = *(const u64*)(g_K2 + src + (size_t)d*TSEQ);
                dV[d] = *(const u64*)(g_V2 + src + (size_t)d*TSEQ);
            }
        }
        __syncthreads();

        if (kt < qt) {
#pragma unroll 8
            for (int jp = 0; jp < NPAIR; jp++) PAIR_BODY(jp, false)
        } else {
            // diagonal tile: pairs 0..qg-1 fully valid; pair qg masks q0's odd key
            for (int jp = 0; jp < qg; jp++) PAIR_BODY(jp, false)
            PAIR_BODY(qg, true)
        }
    }

    float L0lo, L0hi, L1lo, L1hi;
    f2_unpack(l0, L0lo, L0hi);
    f2_unpack(l1, L1lo, L1hi);
    float inv0 = __frcp_rn(L0lo + L0hi);
    float inv1 = __frcp_rn(L1lo + L1hi);

    float r0[8], r1[8];
#pragma unroll
    for (int d = 0; d < 8; d++) {
        float lo, hi;
        f2_unpack(a0[d], lo, hi); r0[d] = (lo + hi) * inv0;
        f2_unpack(a1[d], lo, hi); r1[d] = (lo + hi) * inv1;
    }
    float4* z0 = (float4*)&g_Z[((size_t)b * TSEQ + i0) * NDIM + h * HS];
    float4* z1 = (float4*)&g_Z[((size_t)b * TSEQ + i0 + 1) * NDIM + h * HS];
    z0[0] = make_float4(r0[0], r0[1], r0[2], r0[3]);
    z0[1] = make_float4(r0[4], r0[5], r0[6], r0[7]);
    z1[0] = make_float4(r1[0], r1[1], r1[2], r1[3]);
    z1[1] = make_float4(r1[4], r1[5], r1[6], r1[7]);
#undef PAIR_BODY
}

// ---------------------------------------------------------------------------
// Kernel 3: output projection. grid=(128,2): blockIdx.y picks 16 output dims.
// ---------------------------------------------------------------------------
__global__ __launch_bounds__(256) void proj_kernel(
    const float* __restrict__ Wp, const float* __restrict__ bp,
    float* __restrict__ out)
{
    __shared__ float4 sW[128];
    __shared__ float  sB[16];
    int tid  = threadIdx.x;
    int half = blockIdx.y;
    if (tid < 128) sW[tid] = ((const float4*)Wp)[half*128 + tid];
    if (tid < 16)  sB[tid] = bp[half*16 + tid];
    __syncthreads();

    int tok = blockIdx.x * 256 + tid;
    float zv[32];
    const float4* zr = (const float4*)&g_Z[(size_t)tok * NDIM];
#pragma unroll
    for (int i = 0; i < 8; i++) {
        float4 v = zr[i];
        zv[4*i] = v.x; zv[4*i+1] = v.y; zv[4*i+2] = v.z; zv[4*i+3] = v.w;
    }
    float o[16];
#pragma unroll
    for (int d = 0; d < 16; d++) {
        float acc = sB[d];
#pragma unroll
        for (int c = 0; c < 8; c++) {
            float4 w = sW[d*8 + c];
            acc = fmaf(zv[4*c],   w.x,
                  fmaf(zv[4*c+1], w.y,
                  fmaf(zv[4*c+2], w.z,
                  fmaf(zv[4*c+3], w.w, acc))));
        }
        o[d] = acc;
    }
    float4* op = (float4*)&out[(size_t)tok * NDIM + half*16];
#pragma unroll
    for (int c = 0; c < 4; c++)
        op[c] = make_float4(o[4*c], o[4*c+1], o[4*c+2], o[4*c+3]);
}

// ---------------------------------------------------------------------------
extern "C" void kernel_launch(void* const* d_in, const int* in_sizes, int n_in,
                              void* d_out, int out_size)
{
    const float* x  = (const float*)d_in[0];
    const float* Wq = (const float*)d_in[1];
    const float* bq = (const float*)d_in[2];
    const float* Wk = (const float*)d_in[3];
    const float* bk = (const float*)d_in[4];
    const float* Wv = (const float*)d_in[5];
    const float* bv = (const float*)d_in[6];
    const float* Wp = (const float*)d_in[7];
    const float* bp = (const float*)d_in[8];
    float* out = (float*)d_out;

    qkv_kernel<<<dim3((BSZ*TSEQ)/256, 3), 256>>>(x, Wq, bq, Wk, bk, Wv, bv);
    attn_kernel<<<dim3(BSZ, TSEQ/TQ), 128>>>();
    proj_kernel<<<dim3((BSZ*TSEQ)/256, 2), 256>>>(Wp, bp, out);
}

// round 3
// speedup vs baseline: 2.3173x; 1.0824x over previous
#include <cuda_runtime.h>

#define BSZ   16
#define TSEQ  2048
#define NDIM  32
#define NH    4
#define HS    8
#define TQ    64            // queries per attn block
#define TK    64            // keys per smem tile
#define NPAIR (TK/2)
#define RS    10            // smem row stride in u64 (80B)
#define HSZ   (NPAIR*RS + 2)
#define NS    4             // key-split chunks (8 tiles = 512 keys each)
#define QT_N  (TSEQ/TQ)     // 32 query tiles

// Scratch (device globals — no allocation allowed)
__device__ float g_Q    [BSZ*NH*TSEQ*HS];          // [b][h][t][d]
__device__ float g_K2   [BSZ*NH*HS*TSEQ];          // [b][h][d][t] dim-major
__device__ float g_V2   [BSZ*NH*HS*TSEQ];          // [b][h][d][t]
__device__ float g_Apart[NS*BSZ*TSEQ*NDIM];        // [s][b][t][h*8+d] partial sums
__device__ float g_Lpart[NS*BSZ*TSEQ*NH];          // [s][b][t][h]    partial norms

typedef unsigned long long u64;

__device__ __forceinline__ u64 f2_pack(float lo, float hi){
    u64 r; asm("mov.b64 %0,{%1,%2};":"=l"(r):"f"(lo),"f"(hi)); return r;
}
__device__ __forceinline__ void f2_unpack(u64 v, float& lo, float& hi){
    asm("mov.b64 {%0,%1},%2;":"=f"(lo),"=f"(hi):"l"(v));
}
__device__ __forceinline__ u64 f2_fma(u64 a, u64 b, u64 c){
    u64 d; asm("fma.rn.f32x2 %0,%1,%2,%3;":"=l"(d):"l"(a),"l"(b),"l"(c)); return d;
}
__device__ __forceinline__ u64 f2_mul(u64 a, u64 b){
    u64 d; asm("mul.rn.f32x2 %0,%1,%2;":"=l"(d):"l"(a),"l"(b)); return d;
}
__device__ __forceinline__ u64 f2_add(u64 a, u64 b){
    u64 d; asm("add.rn.f32x2 %0,%1,%2;":"=l"(d):"l"(a),"l"(b)); return d;
}
__device__ __forceinline__ float fast_ex2(float x){
    float r; asm("ex2.approx.ftz.f32 %0,%1;":"=f"(r):"f"(x)); return r;
}

// ---------------------------------------------------------------------------
// Kernel 1: QKV projection. grid=(32, 6), block=256.
// blockIdx.y: m = y>>1 selects {Q,K,V}, half = y&1 selects 16 output dims.
// One thread per token; computes 16 dims -> lower regs, higher occupancy.
// ---------------------------------------------------------------------------
__global__ __launch_bounds__(256) void qkv_kernel(
    const float* __restrict__ x,
    const float* __restrict__ Wq, const float* __restrict__ bq,
    const float* __restrict__ Wk, const float* __restrict__ bk,
    const float* __restrict__ Wv, const float* __restrict__ bv)
{
    __shared__ float4 sW[128];   // 16 rows x 32 cols
    __shared__ float  sB[16];
    int m    = blockIdx.y >> 1;
    int half = blockIdx.y & 1;
    int tid  = threadIdx.x;
    const float* W  = (m == 0) ? Wq : (m == 1) ? Wk : Wv;
    const float* bb = (m == 0) ? bq : (m == 1) ? bk : bv;
    if (tid < 128) sW[tid] = ((const float4*)W)[half*128 + tid];
    if (tid < 16)  sB[tid] = bb[half*16 + tid];
    __syncthreads();

    int tok = blockIdx.x * 256 + tid;
    int b = tok >> 11;
    int t = tok & (TSEQ - 1);

    float xv[32];
    const float4* xr = (const float4*)(x + (size_t)tok * NDIM);
#pragma unroll
    for (int i = 0; i < 8; i++) {
        float4 v = xr[i];
        xv[4*i] = v.x; xv[4*i+1] = v.y; xv[4*i+2] = v.z; xv[4*i+3] = v.w;
    }

    float out[16];
#pragma unroll
    for (int d = 0; d < 16; d++) {
        float acc = sB[d];
#pragma unroll
        for (int c = 0; c < 8; c++) {
            float4 w = sW[d*8 + c];
            acc = fmaf(xv[4*c],   w.x,
                  fmaf(xv[4*c+1], w.y,
                  fmaf(xv[4*c+2], w.z,
                  fmaf(xv[4*c+3], w.w, acc))));
        }
        out[d] = acc;
    }

    if (m == 0) {
        // dims half*16 .. half*16+15 -> heads 2*half, 2*half+1
#pragma unroll
        for (int hh = 0; hh < 2; hh++) {
            int h = half*2 + hh;
            float4* p = (float4*)&g_Q[(((size_t)(b*NH + h)) * TSEQ + t) * HS];
            p[0] = make_float4(out[hh*8+0], out[hh*8+1], out[hh*8+2], out[hh*8+3]);
            p[1] = make_float4(out[hh*8+4], out[hh*8+5], out[hh*8+6], out[hh*8+7]);
        }
    } else {
        float* dst = (m == 1) ? g_K2 : g_V2;
#pragma unroll
        for (int d = 0; d < 16; d++) {
            int dg = half*16 + d;
            int h = dg >> 3, dd = dg & 7;
            dst[(((size_t)(b*NH + h)) * HS + dd) * TSEQ + t] = out[d];
        }
    }
}

// ---------------------------------------------------------------------------
// Kernel 2: causal attention, split-K.
// grid = (NS, QT_N, BSZ); x = key-chunk s (fastest, for launch-order balance),
// y -> qt = QT_N-1-y (heavy rows first), z = batch.
// Block: 128 thr = 4 warps; warp = head; lane = 2 queries (f32x2-packed pairs).
// Each block handles key tiles [8s, min(8s+7, qt)] and writes PARTIAL
// (sum p*v, sum p) — no max tracking, so partials combine by plain addition.
// ---------------------------------------------------------------------------
__global__ __launch_bounds__(128) void attn_kernel()
{
    int s  = blockIdx.x;
    int qt = (QT_N - 1) - (int)blockIdx.y;
    int b  = blockIdx.z;
    if (qt < 8*s) return;      // chunk beyond causal horizon: no work

    __shared__ u64 sm[2*NH*HSZ];

    int tid = threadIdx.x;
    int h   = tid >> 5;
    int qg  = tid & 31;
    int i0  = qt * TQ + 2*qg;

    const float SC = 0.35355339059327f * 1.44269504088896f; // 1/sqrt(8)*log2(e)

    const float4* qp = (const float4*)&g_Q[(((size_t)(b*NH + h)) * TSEQ + i0) * HS];
    float4 qA = qp[0], qB = qp[1], qC = qp[2], qD = qp[3];
    u64 q0[8], q1[8];
    q0[0]=f2_pack(qA.x*SC,qA.x*SC); q0[1]=f2_pack(qA.y*SC,qA.y*SC);
    q0[2]=f2_pack(qA.z*SC,qA.z*SC); q0[3]=f2_pack(qA.w*SC,qA.w*SC);
    q0[4]=f2_pack(qB.x*SC,qB.x*SC); q0[5]=f2_pack(qB.y*SC,qB.y*SC);
    q0[6]=f2_pack(qB.z*SC,qB.z*SC); q0[7]=f2_pack(qB.w*SC,qB.w*SC);
    q1[0]=f2_pack(qC.x*SC,qC.x*SC); q1[1]=f2_pack(qC.y*SC,qC.y*SC);
    q1[2]=f2_pack(qC.z*SC,qC.z*SC); q1[3]=f2_pack(qC.w*SC,qC.w*SC);
    q1[4]=f2_pack(qD.x*SC,qD.x*SC); q1[5]=f2_pack(qD.y*SC,qD.y*SC);
    q1[6]=f2_pack(qD.z*SC,qD.z*SC); q1[7]=f2_pack(qD.w*SC,qD.w*SC);

    u64 a0[8], a1[8];
#pragma unroll
    for (int d = 0; d < 8; d++) { a0[d] = 0ull; a1[d] = 0ull; }
    u64 l0 = 0ull, l1 = 0ull;

    const u64* kr = sm + h*HSZ;
    const u64* vr = sm + NH*HSZ + h*HSZ;

#define PAIR_BODY(JP, MASK0)                                               \
    {                                                                      \
        const ulonglong2* kp2 = (const ulonglong2*)(kr + (JP)*RS);         \
        ulonglong2 ka = kp2[0], kb = kp2[1], kc = kp2[2], kd = kp2[3];     \
        u64 t0 = f2_mul(q0[0], ka.x);                                      \
        t0 = f2_fma(q0[1], ka.y, t0);                                      \
        t0 = f2_fma(q0[2], kb.x, t0);                                      \
        t0 = f2_fma(q0[3], kb.y, t0);                                      \
        t0 = f2_fma(q0[4], kc.x, t0);                                      \
        t0 = f2_fma(q0[5], kc.y, t0);                                      \
        t0 = f2_fma(q0[6], kd.x, t0);                                      \
        t0 = f2_fma(q0[7], kd.y, t0);                                      \
        u64 t1 = f2_mul(q1[0], ka.x);                                      \
        t1 = f2_fma(q1[1], ka.y, t1);                                      \
        t1 = f2_fma(q1[2], kb.x, t1);                                      \
        t1 = f2_fma(q1[3], kb.y, t1);                                      \
        t1 = f2_fma(q1[4], kc.x, t1);                                      \
        t1 = f2_fma(q1[5], kc.y, t1);                                      \
        t1 = f2_fma(q1[6], kd.x, t1);                                      \
        t1 = f2_fma(q1[7], kd.y, t1);                                      \
        float s0e, s0o, s1e, s1o;                                          \
        f2_unpack(t0, s0e, s0o);                                           \
        f2_unpack(t1, s1e, s1o);                                           \
        float p0o = (MASK0) ? 0.0f : fast_ex2(s0o);                        \
        u64 pp0 = f2_pack(fast_ex2(s0e), p0o);                             \
        u64 pp1 = f2_pack(fast_ex2(s1e), fast_ex2(s1o));                   \
        l0 = f2_add(l0, pp0);                                              \
        l1 = f2_add(l1, pp1);                                              \
        const ulonglong2* vp2 = (const ulonglong2*)(vr + (JP)*RS);         \
        ulonglong2 va = vp2[0], vb = vp2[1], vc = vp2[2], vd = vp2[3];     \
        a0[0] = f2_fma(pp0, va.x, a0[0]);  a1[0] = f2_fma(pp1, va.x, a1[0]); \
        a0[1] = f2_fma(pp0, va.y, a0[1]);  a1[1] = f2_fma(pp1, va.y, a1[1]); \
        a0[2] = f2_fma(pp0, vb.x, a0[2]);  a1[2] = f2_fma(pp1, vb.x, a1[2]); \
        a0[3] = f2_fma(pp0, vb.y, a0[3]);  a1[3] = f2_fma(pp1, vb.y, a1[3]); \
        a0[4] = f2_fma(pp0, vc.x, a0[4]);  a1[4] = f2_fma(pp1, vc.x, a1[4]); \
        a0[5] = f2_fma(pp0, vc.y, a0[5]);  a1[5] = f2_fma(pp1, vc.y, a1[5]); \
        a0[6] = f2_fma(pp0, vd.x, a0[6]);  a1[6] = f2_fma(pp1, vd.x, a1[6]); \
        a0[7] = f2_fma(pp0, vd.y, a0[7]);  a1[7] = f2_fma(pp1, vd.y, a1[7]); \
    }

    int kt1 = 8*s + 7; if (kt1 > qt) kt1 = qt;
    for (int kt = 8*s; kt <= kt1; kt++) {
        int j0 = kt * TK;
        __syncthreads();
        {
            size_t src = ((size_t)(b*NH + h)) * HS * TSEQ + (j0 + 2*qg);
            u64* dK = sm + h*HSZ + qg*RS;
            u64* dV = sm + NH*HSZ + h*HSZ + qg*RS;
#pragma unroll
            for (int d = 0; d < 8; d++) {
                dK[d] = *(const u64*)(g_K2 + src + (size_t)d*TSEQ);
                dV[d] = *(const u64*)(g_V2 + src + (size_t)d*TSEQ);
            }
        }
        __syncthreads();

        if (kt < qt) {
#pragma unroll 8
            for (int jp = 0; jp < NPAIR; jp++) PAIR_BODY(jp, false)
        } else {
            for (int jp = 0; jp < qg; jp++) PAIR_BODY(jp, false)
            PAIR_BODY(qg, true)
        }
    }

    // store raw partials (no normalization here)
    float L0lo, L0hi, L1lo, L1hi;
    f2_unpack(l0, L0lo, L0hi);
    f2_unpack(l1, L1lo, L1hi);

    float r0[8], r1[8];
#pragma unroll
    for (int d = 0; d < 8; d++) {
        float lo, hi;
        f2_unpack(a0[d], lo, hi); r0[d] = lo + hi;
        f2_unpack(a1[d], lo, hi); r1[d] = lo + hi;
    }
    size_t base = (((size_t)s*BSZ + b) * TSEQ + i0);
    float4* z0 = (float4*)&g_Apart[base * NDIM + h*HS];
    float4* z1 = (float4*)&g_Apart[(base + 1) * NDIM + h*HS];
    z0[0] = make_float4(r0[0], r0[1], r0[2], r0[3]);
    z0[1] = make_float4(r0[4], r0[5], r0[6], r0[7]);
    z1[0] = make_float4(r1[0], r1[1], r1[2], r1[3]);
    z1[1] = make_float4(r1[4], r1[5], r1[6], r1[7]);
    g_Lpart[base * NH + h]       = L0lo + L0hi;
    g_Lpart[(base + 1) * NH + h] = L1lo + L1hi;
#undef PAIR_BODY
}

// ---------------------------------------------------------------------------
// Kernel 3: merge split-K partials + normalize + output projection.
// grid = (128, 2); blockIdx.y picks 16 output dims. One thread per token.
// Token t has (t>>9)+1 valid key-chunks.
// ---------------------------------------------------------------------------
__global__ __launch_bounds__(256) void proj_kernel(
    const float* __restrict__ Wp, const float* __restrict__ bp,
    float* __restrict__ out)
{
    __shared__ float4 sW[128];
    __shared__ float  sB[16];
    int tid  = threadIdx.x;
    int half = blockIdx.y;
    if (tid < 128) sW[tid] = ((const float4*)Wp)[half*128 + tid];
    if (tid < 16)  sB[tid] = bp[half*16 + tid];
    __syncthreads();

    int tok = blockIdx.x * 256 + tid;
    int b = tok >> 11;
    int t = tok & (TSEQ - 1);
    int nS = (t >> 9) + 1;     // valid key-chunks for this token

    float av[32];
    float lv[4];
#pragma unroll
    for (int i = 0; i < 32; i++) av[i] = 0.f;
#pragma unroll
    for (int h = 0; h < 4; h++) lv[h] = 0.f;

    for (int sI = 0; sI < nS; sI++) {
        size_t base = (((size_t)sI*BSZ + b) * TSEQ + t);
        const float4* ap = (const float4*)&g_Apart[base * NDIM];
#pragma unroll
        for (int i = 0; i < 8; i++) {
            float4 v = ap[i];
            av[4*i] += v.x; av[4*i+1] += v.y; av[4*i+2] += v.z; av[4*i+3] += v.w;
        }
        const float4 lp = *(const float4*)&g_Lpart[base * NH];
        lv[0] += lp.x; lv[1] += lp.y; lv[2] += lp.z; lv[3] += lp.w;
    }

    float zv[32];
#pragma unroll
    for (int h = 0; h < 4; h++) {
        float inv = __frcp_rn(lv[h]);
#pragma unroll
        for (int d = 0; d < 8; d++) zv[h*8+d] = av[h*8+d] * inv;
    }

    float o[16];
#pragma unroll
    for (int d = 0; d < 16; d++) {
        float acc = sB[d];
#pragma unroll
        for (int c = 0; c < 8; c++) {
            float4 w = sW[d*8 + c];
            acc = fmaf(zv[4*c],   w.x,
                  fmaf(zv[4*c+1], w.y,
                  fmaf(zv[4*c+2], w.z,
                  fmaf(zv[4*c+3], w.w, acc))));
        }
        o[d] = acc;
    }
    float4* op = (float4*)&out[(size_t)tok * NDIM + half*16];
#pragma unroll
    for (int c = 0; c < 4; c++)
        op[c] = make_float4(o[4*c], o[4*c+1], o[4*c+2], o[4*c+3]);
}

// ---------------------------------------------------------------------------
extern "C" void kernel_launch(void* const* d_in, const int* in_sizes, int n_in,
                              void* d_out, int out_size)
{
    const float* x  = (const float*)d_in[0];
    const float* Wq = (const float*)d_in[1];
    const float* bq = (const float*)d_in[2];
    const float* Wk = (const float*)d_in[3];
    const float* bk = (const float*)d_in[4];
    const float* Wv = (const float*)d_in[5];
    const float* bv = (const float*)d_in[6];
    const float* Wp = (const float*)d_in[7];
    const float* bp = (const float*)d_in[8];
    float* out = (float*)d_out;

    qkv_kernel<<<dim3((BSZ*TSEQ)/256, 6), 256>>>(x, Wq, bq, Wk, bk, Wv, bv);
    attn_kernel<<<dim3(NS, QT_N, BSZ), 128>>>();
    proj_kernel<<<dim3((BSZ*TSEQ)/256, 2), 256>>>(Wp, bp, out);
}

// round 4
// speedup vs baseline: 4.5700x; 1.9722x over previous
#include <cuda_runtime.h>
#include <cuda_fp16.h>

#define BSZ   16
#define TSEQ  2048
#define NDIM  32
#define NH    4
#define HS    8
#define NS    4               // key-split chunks (8 tiles of 64 = 512 keys)
#define QB_N  (TSEQ/64)       // 32 query bands of 64

// Scratch (device globals — no allocation allowed)
__device__ unsigned g_Q2[BSZ*NH*TSEQ*HS];   // tf32 pairs: [tok][t] = (d=t, d=t+4), pre-scaled
__device__ unsigned g_K2[BSZ*NH*TSEQ*HS];   // tf32 pairs
__device__ __half   g_Vt[BSZ*NH*HS*TSEQ];   // f16, [b][h][d][tok]
__device__ float    g_Apart[NS*BSZ*TSEQ*NDIM];
__device__ float    g_Lpart[NS*BSZ*TSEQ*NH];

typedef unsigned u32;

__device__ __forceinline__ u32 to_tf32(float x){
    u32 r; asm("cvt.rna.tf32.f32 %0,%1;":"=r"(r):"f"(x)); return r;
}
__device__ __forceinline__ float fast_ex2(float x){
    float r; asm("ex2.approx.ftz.f32 %0,%1;":"=f"(r):"f"(x)); return r;
}
// pack(lo,hi): d.lo = lo, d.hi = hi  (cvt packs first source into UPPER half)
__device__ __forceinline__ u32 pack_h2(float lo, float hi){
    u32 r; asm("cvt.rn.f16x2.f32 %0, %1, %2;" : "=r"(r) : "f"(hi), "f"(lo)); return r;
}
// D(16x8,f32) = A(16x8,tf32) * B(8x8,tf32), C = 0
__device__ __forceinline__ void mma_qk(float* d, const u32* a, u32 b0, u32 b1){
    asm("mma.sync.aligned.m16n8k8.row.col.f32.tf32.tf32.f32 "
        "{%0,%1,%2,%3},{%4,%5,%6,%7},{%8,%9},{%10,%11,%12,%13};"
        : "=f"(d[0]),"=f"(d[1]),"=f"(d[2]),"=f"(d[3])
        : "r"(a[0]),"r"(a[1]),"r"(a[2]),"r"(a[3]), "r"(b0),"r"(b1),
          "f"(0.f),"f"(0.f),"f"(0.f),"f"(0.f));
}
// D(16x8,f32) += A(16x16,f16) * B(16x8,f16)
__device__ __forceinline__ void mma_pv(float* d, u32 a0,u32 a1,u32 a2,u32 a3, u32 b0,u32 b1){
    asm("mma.sync.aligned.m16n8k16.row.col.f32.f16.f16.f32 "
        "{%0,%1,%2,%3},{%4,%5,%6,%7},{%8,%9},{%0,%1,%2,%3};"
        : "+f"(d[0]),"+f"(d[1]),"+f"(d[2]),"+f"(d[3])
        : "r"(a0),"r"(a1),"r"(a2),"r"(a3), "r"(b0),"r"(b1));
}

// ---------------------------------------------------------------------------
// Kernel 1: QKV projection. grid=(128,3): y = matrix. Thread = token, 32 dims.
// Q: *scale, tf32-rounded, pair layout. K: tf32 pair layout. V: f16 [d][t].
// ---------------------------------------------------------------------------
__global__ __launch_bounds__(256) void qkv_kernel(
    const float* __restrict__ x,
    const float* __restrict__ Wq, const float* __restrict__ bq,
    const float* __restrict__ Wk, const float* __restrict__ bk,
    const float* __restrict__ Wv, const float* __restrict__ bv)
{
    __shared__ float4 sW[256];
    __shared__ float  sB[32];
    int m   = blockIdx.y;
    int tid = threadIdx.x;
    const float* W  = (m == 0) ? Wq : (m == 1) ? Wk : Wv;
    const float* bb = (m == 0) ? bq : (m == 1) ? bk : bv;
    sW[tid] = ((const float4*)W)[tid];
    if (tid < 32) sB[tid] = bb[tid];
    __syncthreads();

    int tok = blockIdx.x * 256 + tid;
    int b = tok >> 11;
    int t = tok & (TSEQ - 1);

    float xv[32];
    const float4* xr = (const float4*)(x + (size_t)tok * NDIM);
#pragma unroll
    for (int i = 0; i < 8; i++) {
        float4 v = xr[i];
        xv[4*i] = v.x; xv[4*i+1] = v.y; xv[4*i+2] = v.z; xv[4*i+3] = v.w;
    }

    float out[32];
#pragma unroll
    for (int d = 0; d < 32; d++) {
        float acc = sB[d];
#pragma unroll
        for (int c = 0; c < 8; c++) {
            float4 w = sW[d*8 + c];
            acc = fmaf(xv[4*c],   w.x,
                  fmaf(xv[4*c+1], w.y,
                  fmaf(xv[4*c+2], w.z,
                  fmaf(xv[4*c+3], w.w, acc))));
        }
        out[d] = acc;
    }

    const float SC = 0.35355339059327f * 1.44269504088896f; // 1/sqrt(8)*log2(e)
    if (m == 0) {
#pragma unroll
        for (int h = 0; h < NH; h++)
#pragma unroll
            for (int j = 0; j < 4; j++) {
                uint2 v = make_uint2(to_tf32(out[h*8+j]*SC), to_tf32(out[h*8+j+4]*SC));
                *(uint2*)&g_Q2[(((size_t)(b*NH+h))*TSEQ + t)*8 + j*2] = v;
            }
    } else if (m == 1) {
#pragma unroll
        for (int h = 0; h < NH; h++)
#pragma unroll
            for (int j = 0; j < 4; j++) {
                uint2 v = make_uint2(to_tf32(out[h*8+j]), to_tf32(out[h*8+j+4]));
                *(uint2*)&g_K2[(((size_t)(b*NH+h))*TSEQ + t)*8 + j*2] = v;
            }
    } else {
#pragma unroll
        for (int d = 0; d < 32; d++) {
            int h = d >> 3, dd = d & 7;
            g_Vt[(((size_t)(b*NH+h))*HS + dd)*TSEQ + t] = __float2half_rn(out[d]);
        }
    }
}

// ---------------------------------------------------------------------------
// Kernel 2: causal attention on tensor cores, split-K, no smem, no syncs.
// grid=(NS, QB_N, BSZ), block=256 (8 warps). Warp = (head h, 32-query sub).
// Per 64-key tile: 16x tf32 m16n8k8 (QK), exp2 on D frags, f16x2 pack,
// 8x f16 m16n8k16 (PV). Partials (sum p*v, sum p) -> g_Apart/g_Lpart.
// ---------------------------------------------------------------------------
__global__ __launch_bounds__(256) void attn_kernel()
{
    int s  = blockIdx.x;
    int qb = (QB_N - 1) - (int)blockIdx.y;   // heavy bands first
    int b  = blockIdx.z;
    if (8*s > qb) return;

    int wid  = threadIdx.x >> 5;
    int lane = threadIdx.x & 31;
    int h    = wid & 3;
    int sub  = wid >> 2;
    int g    = lane >> 2;     // groupID (row within fragment)
    int t    = lane & 3;      // thread-in-quad (col index)
    int q0   = qb*64 + sub*32;

    const u32*    Qp = g_Q2 + ((size_t)(b*NH + h))*TSEQ*8;
    const u32*    Kp = g_K2 + ((size_t)(b*NH + h))*TSEQ*8;
    const __half* Vp = g_Vt + ((size_t)(b*NH + h))*HS*TSEQ;

    // Q fragments: 2 row-groups of 16 (rows q0.., q0+16..)
    u32 qa[2][4];
#pragma unroll
    for (int grp = 0; grp < 2; grp++) {
        uint2 lo = *(const uint2*)&Qp[(size_t)(q0 + 16*grp +     g)*8 + t*2];
        uint2 hi = *(const uint2*)&Qp[(size_t)(q0 + 16*grp + 8 + g)*8 + t*2];
        qa[grp][0] = lo.x; qa[grp][2] = lo.y;
        qa[grp][1] = hi.x; qa[grp][3] = hi.y;
    }

    float z[2][4] = {{0.f,0.f,0.f,0.f},{0.f,0.f,0.f,0.f}};
    float l4[4]   = {0.f,0.f,0.f,0.f};

    int ktd = qb;                                  // diagonal 64-key tile
    int kt1 = 8*s + 7; if (kt1 > ktd) kt1 = ktd;

    for (int kt = 8*s; kt <= kt1; kt++) {
        int j0 = kt*64;
        // K B-fragments: 8 chunks of 8 keys
        u32 kb0[8], kb1[8];
#pragma unroll
        for (int c = 0; c < 8; c++) {
            uint2 kk = *(const uint2*)&Kp[(size_t)(j0 + 8*c + g)*8 + t*2];
            kb0[c] = kk.x; kb1[c] = kk.y;
        }
        // V B-fragments: 4 chunks of 16 keys
        u32 vb0[4], vb1[4];
#pragma unroll
        for (int cc = 0; cc < 4; cc++) {
            const __half* vrow = Vp + (size_t)g*TSEQ + j0 + 16*cc;
            vb0[cc] = *(const u32*)(vrow + 2*t);
            vb1[cc] = *(const u32*)(vrow + 8 + 2*t);
        }
        bool diag = (kt == ktd);

#pragma unroll
        for (int grp = 0; grp < 2; grp++) {
            int r0 = q0 + 16*grp + g;
            float p[8][4];
#pragma unroll
            for (int c = 0; c < 8; c++) mma_qk(p[c], qa[grp], kb0[c], kb1[c]);
#pragma unroll
            for (int c = 0; c < 8; c++) {
                int col = j0 + 8*c + 2*t;
                float e0, e1, e2, e3;
                if (diag) {
                    e0 = (col   <= r0  ) ? fast_ex2(p[c][0]) : 0.f;
                    e1 = (col+1 <= r0  ) ? fast_ex2(p[c][1]) : 0.f;
                    e2 = (col   <= r0+8) ? fast_ex2(p[c][2]) : 0.f;
                    e3 = (col+1 <= r0+8) ? fast_ex2(p[c][3]) : 0.f;
                } else {
                    e0 = fast_ex2(p[c][0]); e1 = fast_ex2(p[c][1]);
                    e2 = fast_ex2(p[c][2]); e3 = fast_ex2(p[c][3]);
                }
                p[c][0] = e0; p[c][1] = e1; p[c][2] = e2; p[c][3] = e3;
                l4[2*grp+0] += e0 + e1;
                l4[2*grp+1] += e2 + e3;
            }
#pragma unroll
            for (int cc = 0; cc < 4; cc++) {
                u32 a0 = pack_h2(p[2*cc  ][0], p[2*cc  ][1]);
                u32 a1 = pack_h2(p[2*cc  ][2], p[2*cc  ][3]);
                u32 a2 = pack_h2(p[2*cc+1][0], p[2*cc+1][1]);
                u32 a3 = pack_h2(p[2*cc+1][2], p[2*cc+1][3]);
                mma_pv(z[grp], a0, a1, a2, a3, vb0[cc], vb1[cc]);
            }
        }
    }

    // epilogue: quad-reduce l, store partials
#pragma unroll
    for (int grp = 0; grp < 2; grp++) {
#pragma unroll
        for (int rr = 0; rr < 2; rr++) {
            float ls = l4[2*grp + rr];
            ls += __shfl_xor_sync(0xffffffffu, ls, 1);
            ls += __shfl_xor_sync(0xffffffffu, ls, 2);
            int row = q0 + 16*grp + 8*rr + g;
            size_t base = ((size_t)s*BSZ + b)*TSEQ + row;
            *(float2*)&g_Apart[base*NDIM + h*HS + 2*t] =
                make_float2(z[grp][2*rr], z[grp][2*rr+1]);
            if (t == 0) g_Lpart[base*NH + h] = ls;
        }
    }
}

// ---------------------------------------------------------------------------
// Kernel 3: merge split-K partials + normalize + output projection.
// grid = (128, 2); blockIdx.y picks 16 output dims. One thread per token.
// ---------------------------------------------------------------------------
__global__ __launch_bounds__(256) void proj_kernel(
    const float* __restrict__ Wp, const float* __restrict__ bp,
    float* __restrict__ out)
{
    __shared__ float4 sW[128];
    __shared__ float  sB[16];
    int tid  = threadIdx.x;
    int half = blockIdx.y;
    if (tid < 128) sW[tid] = ((const float4*)Wp)[half*128 + tid];
    if (tid < 16)  sB[tid] = bp[half*16 + tid];
    __syncthreads();

    int tok = blockIdx.x * 256 + tid;
    int b = tok >> 11;
    int t = tok & (TSEQ - 1);
    int nS = (t >> 9) + 1;

    float av[32];
    float lv[4];
#pragma unroll
    for (int i = 0; i < 32; i++) av[i] = 0.f;
#pragma unroll
    for (int h = 0; h < 4; h++) lv[h] = 0.f;

    for (int sI = 0; sI < nS; sI++) {
        size_t base = (((size_t)sI*BSZ + b) * TSEQ + t);
        const float4* ap = (const float4*)&g_Apart[base * NDIM];
#pragma unroll
        for (int i = 0; i < 8; i++) {
            float4 v = ap[i];
            av[4*i] += v.x; av[4*i+1] += v.y; av[4*i+2] += v.z; av[4*i+3] += v.w;
        }
        const float4 lp = *(const float4*)&g_Lpart[base * NH];
        lv[0] += lp.x; lv[1] += lp.y; lv[2] += lp.z; lv[3] += lp.w;
    }

    float zv[32];
#pragma unroll
    for (int h = 0; h < 4; h++) {
        float inv = __frcp_rn(lv[h]);
#pragma unroll
        for (int d = 0; d < 8; d++) zv[h*8+d] = av[h*8+d] * inv;
    }

    float o[16];
#pragma unroll
    for (int d = 0; d < 16; d++) {
        float acc = sB[d];
#pragma unroll
        for (int c = 0; c < 8; c++) {
            float4 w = sW[d*8 + c];
            acc = fmaf(zv[4*c],   w.x,
                  fmaf(zv[4*c+1], w.y,
                  fmaf(zv[4*c+2], w.z,
                  fmaf(zv[4*c+3], w.w, acc))));
        }
        o[d] = acc;
    }
    float4* op = (float4*)&out[(size_t)tok * NDIM + half*16];
#pragma unroll
    for (int c = 0; c < 4; c++)
        op[c] = make_float4(o[4*c], o[4*c+1], o[4*c+2], o[4*c+3]);
}

// ---------------------------------------------------------------------------
extern "C" void kernel_launch(void* const* d_in, const int* in_sizes, int n_in,
                              void* d_out, int out_size)
{
    const float* x  = (const float*)d_in[0];
    const float* Wq = (const float*)d_in[1];
    const float* bq = (const float*)d_in[2];
    const float* Wk = (const float*)d_in[3];
    const float* bk = (const float*)d_in[4];
    const float* Wv = (const float*)d_in[5];
    const float* bv = (const float*)d_in[6];
    const float* Wp = (const float*)d_in[7];
    const float* bp = (const float*)d_in[8];
    float* out = (float*)d_out;

    qkv_kernel<<<dim3((BSZ*TSEQ)/256, 3), 256>>>(x, Wq, bq, Wk, bk, Wv, bv);
    attn_kernel<<<dim3(NS, QB_N, BSZ), 256>>>();
    proj_kernel<<<dim3((BSZ*TSEQ)/256, 2), 256>>>(Wp, bp, out);
}